// round 5
// baseline (speedup 1.0000x reference)
#include <cuda_runtime.h>
#include <cuda.h>
#include <cstdint>

// ============================================================
// QuantizedConv2d exact int conv via split-weight int8 mma.sync GEMM
//   x[8,128,56,56], w[256,128,3,3], bias[256], shift=16 (structural)
//   out[8,256,56,56] = (conv(x,w)+bias) >> 16
// w = (w>>8)*256 + (w&255): hi plane s8, lo plane u8; two s32 GEMMs,
// recombined in i64. Bit-exact.
// Evidence so far: inputs are 4-byte (R3 int64 reads crashed, R4 didn't);
// output buffer is FLOAT-typed (R4 wrote raw int32 -> negative values are
// 0xFFFxxxxx == float32 NaN -> rel_err nan). So: detect input storage
// (i32/f32/i64/f64) at runtime; store output as float for 4-byte worlds.
// ============================================================

static constexpr int NB    = 8;
static constexpr int CIN   = 128;
static constexpr int COUT  = 256;
static constexpr int HW    = 56;
static constexpr int HW2   = HW * HW;           // 3136
static constexpr int NPIX  = NB * HW2;          // 25088
static constexpr int KDIM  = CIN * 9;           // 1152
static constexpr int SHIFT = 16;

static constexpr int CTA_M = 128;               // pixels
static constexpr int CTA_N = 128;               // couts
static constexpr int KC    = 64;                // K chunk
static constexpr int NCHUNK = KDIM / KC;        // 18
static constexpr int M_TILES = NPIX / CTA_M;    // 196
static constexpr int N_TILES = COUT / CTA_N;    // 2
static constexpr int THREADS = 512;             // 16 warps: 4(M) x 4(N)

static constexpr int PITCH   = 80;
static constexpr int SM_TILE = 128 * PITCH;     // 10240
static constexpr int SM_STAGE = 3 * SM_TILE;    // 30720
static constexpr int SM_TOTAL = 2 * SM_STAGE;   // 61440

static constexpr int FLAG_I64 = 0, FLAG_I32 = 1, FLAG_F32 = 2, FLAG_F64 = 3;

// ---------------- scratch (device globals; allocation-free) ----------------
__device__ __align__(128) int8_t g_X[(size_t)NB * CIN * HW2];     // packed x
__device__ __align__(128) int8_t g_A[(size_t)NPIX * KDIM];        // im2col
__device__ __align__(128) int8_t g_W[2 * (size_t)COUT * KDIM];    // hi|lo planes
__device__ int g_flag;

// ---------------- PTX helpers ----------------
__device__ __forceinline__ uint32_t smem_to_u32(const void* p) {
    uint32_t a;
    asm("{ .reg .u64 t; cvta.to.shared.u64 t, %1; cvt.u32.u64 %0, t; }" : "=r"(a) : "l"(p));
    return a;
}
__device__ __forceinline__ void cp16(uint32_t dst, const void* src) {
    asm volatile("cp.async.cg.shared.global [%0], [%1], 16;" :: "r"(dst), "l"(src));
}
#define CP_COMMIT() asm volatile("cp.async.commit_group;" ::: "memory")
#define CP_WAIT(n)  asm volatile("cp.async.wait_group %0;" :: "n"(n) : "memory")

__device__ __forceinline__ void ldsm_x4(uint32_t* r, uint32_t addr) {
    asm volatile("ldmatrix.sync.aligned.m8n8.x4.shared.b16 {%0,%1,%2,%3}, [%4];"
                 : "=r"(r[0]), "=r"(r[1]), "=r"(r[2]), "=r"(r[3]) : "r"(addr));
}
__device__ __forceinline__ void mma_s8s8(int* c, const uint32_t* a, const uint32_t* b) {
    asm volatile("mma.sync.aligned.m16n8k32.row.col.s32.s8.s8.s32 "
                 "{%0,%1,%2,%3}, {%4,%5,%6,%7}, {%8,%9}, {%0,%1,%2,%3};"
                 : "+r"(c[0]), "+r"(c[1]), "+r"(c[2]), "+r"(c[3])
                 : "r"(a[0]), "r"(a[1]), "r"(a[2]), "r"(a[3]), "r"(b[0]), "r"(b[1]));
}
__device__ __forceinline__ void mma_s8u8(int* c, const uint32_t* a, const uint32_t* b) {
    asm volatile("mma.sync.aligned.m16n8k32.row.col.s32.s8.u8.s32 "
                 "{%0,%1,%2,%3}, {%4,%5,%6,%7}, {%8,%9}, {%0,%1,%2,%3};"
                 : "+r"(c[0]), "+r"(c[1]), "+r"(c[2]), "+r"(c[3])
                 : "r"(a[0]), "r"(a[1]), "r"(a[2]), "r"(a[3]), "r"(b[0]), "r"(b[1]));
}

// ---------------- dtype detection (4-way) ----------------
// Inspect first 128 word-pairs of x (<=1KB; buffer >= 12.8MB under any width).
// x values are ints in [-128,128), ~uniform, rarely 0.
//  i64: odd word == sign-extension of even word (always).
//  i32: all words small (|w| < 256).
//  f64: even word == 0 (low mantissa bits of a small int are 0) (always).
//  f32: word == 0 or f32 exponent in [120,140] (always).
__global__ void detect_kernel(const void* xraw) {
    if (threadIdx.x != 0 || blockIdx.x != 0) return;
    const int* w = (const int*)xraw;
    int signext = 0, small = 0, lozero = 0;
    for (int i = 0; i < 128; i++) {
        int lo = w[2 * i], hi = w[2 * i + 1];
        if (hi == (lo < 0 ? -1 : 0)) signext++;
        if (lo >= -256 && lo < 256 && hi >= -256 && hi < 256) small++;
        if (lo == 0) lozero++;
    }
    int f;
    if (signext >= 120)      f = FLAG_I64;
    else if (small >= 120)   f = FLAG_I32;
    else if (lozero >= 100)  f = FLAG_F64;
    else                     f = FLAG_F32;
    g_flag = f;
}

__device__ __forceinline__ long long load_val(const void* p, size_t idx, int flag) {
    if (flag == FLAG_I64) return ((const long long*)p)[idx];
    if (flag == FLAG_I32) return (long long)((const int*)p)[idx];
    if (flag == FLAG_F64) return __double2ll_rn(((const double*)p)[idx]);
    return (long long)__float2ll_rn(((const float*)p)[idx]);
}

// ---------------- kernel 0: pack x -> int8 ----------------
__global__ void packx_kernel(const void* __restrict__ x) {
    int idx = blockIdx.x * blockDim.x + threadIdx.x;
    if (idx >= NB * CIN * HW2) return;
    g_X[idx] = (int8_t)load_val(x, idx, g_flag);
}

// ---------------- kernel 1: weight planes ----------------
__global__ void prepw_kernel(const void* __restrict__ wq) {
    int idx = blockIdx.x * blockDim.x + threadIdx.x;
    if (idx >= COUT * KDIM) return;
    long long w = load_val(wq, idx, g_flag);
    g_W[idx] = (int8_t)(w >> 8);                           // hi (s8)
    g_W[(size_t)COUT * KDIM + idx] = (int8_t)(w & 255);    // lo (u8 bits)
}

// ---------------- kernel 2: im2col (int8) ----------------
__global__ void im2col_kernel() {
    int idx = blockIdx.x * blockDim.x + threadIdx.x;   // NPIX * 288
    if (idx >= NPIX * (KDIM / 4)) return;
    int p  = idx / (KDIM / 4);
    int k4 = idx - p * (KDIM / 4);
    int n  = p / HW2;
    int hw = p - n * HW2;
    int h  = hw / HW;
    int w  = hw - h * HW;
    int8_t vv[4];
#pragma unroll
    for (int t = 0; t < 4; t++) {
        int k   = 4 * k4 + t;
        int cin = k / 9;
        int kk  = k - cin * 9;
        int kh  = kk / 3;
        int kw  = kk - kh * 3;
        int ih  = h + kh - 1;
        int iw  = w + kw - 1;
        int8_t xv = 0;
        if ((unsigned)ih < (unsigned)HW && (unsigned)iw < (unsigned)HW)
            xv = g_X[((size_t)(n * CIN + cin) * HW + ih) * HW + iw];
        vv[t] = xv;
    }
    char4 v; v.x = vv[0]; v.y = vv[1]; v.z = vv[2]; v.w = vv[3];
    *(char4*)&g_A[(size_t)p * KDIM + 4 * k4] = v;
}

// ---------------- kernel 3: GEMM + epilogue ----------------
__device__ __forceinline__ void load_chunk(uint32_t sm, const int8_t* Abase,
                                           const int8_t* Whi, const int8_t* Wlo,
                                           int kc, int tid) {
    int row = tid >> 2;
    int c16 = tid & 3;
    int goff = kc * KC + c16 * 16;
    uint32_t soff = row * PITCH + c16 * 16;
    cp16(sm + soff,                Abase + (size_t)row * KDIM + goff);
    cp16(sm + SM_TILE + soff,      Whi   + (size_t)row * KDIM + goff);
    cp16(sm + 2 * SM_TILE + soff,  Wlo   + (size_t)row * KDIM + goff);
}

__global__ void __launch_bounds__(THREADS, 1)
gemm_kernel(const void* __restrict__ bias, void* __restrict__ outv) {
    extern __shared__ char smem[];
    const uint32_t smb = smem_to_u32(smem);
    const int tid  = threadIdx.x;
    const int lane = tid & 31;
    const int wrp  = tid >> 5;
    const int wm   = wrp & 3;
    const int wn   = wrp >> 2;

    const int mt = blockIdx.x >> 1;
    const int nt = blockIdx.x & 1;

    const int8_t* Abase = g_A + (size_t)mt * CTA_M * KDIM;
    const int8_t* Whi   = g_W + (size_t)nt * CTA_N * KDIM;
    const int8_t* Wlo   = g_W + (size_t)COUT * KDIM + (size_t)nt * CTA_N * KDIM;

    int acch[2][4][4];
    int accl[2][4][4];
#pragma unroll
    for (int mb = 0; mb < 2; mb++)
#pragma unroll
        for (int nb = 0; nb < 4; nb++)
#pragma unroll
            for (int i = 0; i < 4; i++) { acch[mb][nb][i] = 0; accl[mb][nb][i] = 0; }

    load_chunk(smb, Abase, Whi, Wlo, 0, tid);
    CP_COMMIT();

    for (int kc = 0; kc < NCHUNK; kc++) {
        const int buf = kc & 1;
        if (kc + 1 < NCHUNK) {
            load_chunk(smb + (buf ^ 1) * SM_STAGE, Abase, Whi, Wlo, kc + 1, tid);
            CP_COMMIT();
            CP_WAIT(1);
        } else {
            CP_WAIT(0);
        }
        __syncthreads();

        const uint32_t smA  = smb + buf * SM_STAGE;
        const uint32_t smBh = smA + SM_TILE;
        const uint32_t smBl = smA + 2 * SM_TILE;

#pragma unroll
        for (int ks = 0; ks < 2; ks++) {
            uint32_t a[2][4];
#pragma unroll
            for (int mb = 0; mb < 2; mb++) {
                uint32_t addr = smA + (uint32_t)((wm * 32 + mb * 16 + (lane & 15)) * PITCH
                                                 + (ks * 2 + (lane >> 4)) * 16);
                ldsm_x4(a[mb], addr);
            }
            uint32_t bh[2][4], bl[2][4];
#pragma unroll
            for (int nb2 = 0; nb2 < 2; nb2++) {
                uint32_t boff = (uint32_t)((wn * 32 + nb2 * 16 + (lane & 7) + ((lane >> 4) << 3)) * PITCH
                                           + (ks * 2 + ((lane >> 3) & 1)) * 16);
                ldsm_x4(bh[nb2], smBh + boff);
                ldsm_x4(bl[nb2], smBl + boff);
            }
#pragma unroll
            for (int mb = 0; mb < 2; mb++)
#pragma unroll
                for (int nb2 = 0; nb2 < 2; nb2++)
#pragma unroll
                    for (int q = 0; q < 2; q++) {
                        mma_s8s8(acch[mb][nb2 * 2 + q], a[mb], &bh[nb2][q * 2]);
                        mma_s8u8(accl[mb][nb2 * 2 + q], a[mb], &bl[nb2][q * 2]);
                    }
        }
        __syncthreads();
    }

    // ---- epilogue: combine hi/lo in i64, bias, shift, store ----
    // Output buffer is FLOAT-typed (nan evidence): 4-byte worlds -> float32,
    // F64 -> double, I64 -> long long.
    const int flag = g_flag;
#pragma unroll
    for (int mb = 0; mb < 2; mb++) {
#pragma unroll
        for (int nb = 0; nb < 4; nb++) {
            int p0  = mt * CTA_M + wm * 32 + mb * 16 + (lane >> 2);
            int co0 = nt * CTA_N + wn * 32 + nb * 8 + (lane & 3) * 2;
#pragma unroll
            for (int i = 0; i < 4; i++) {
                int p  = p0 + ((i >= 2) ? 8 : 0);
                int co = co0 + (i & 1);
                long long b = load_val(bias, co, flag);
                long long v = (((long long)acch[mb][nb][i] << 8)
                               + (long long)accl[mb][nb][i] + b) >> SHIFT;
                int n  = p / HW2;
                int hw = p - n * HW2;
                size_t oi = ((size_t)(n * COUT + co)) * HW2 + hw;
                if (flag == FLAG_I64)      ((long long*)outv)[oi] = v;
                else if (flag == FLAG_F64) ((double*)outv)[oi] = (double)v;
                else                       ((float*)outv)[oi] = (float)v;
            }
        }
    }
}

// ---------------- launch ----------------
extern "C" void kernel_launch(void* const* d_in, const int* in_sizes, int n_in,
                              void* d_out, int out_size) {
    // Identify inputs by element count (robust to ordering).
    const void* x = nullptr; const void* wq = nullptr; const void* bias = nullptr;
    for (int i = 0; i < n_in; i++) {
        if (in_sizes[i] == NB * CIN * HW2)      x    = d_in[i];
        else if (in_sizes[i] == COUT * KDIM)    wq   = d_in[i];
        else if (in_sizes[i] == COUT)           bias = d_in[i];
    }
    (void)out_size;

    detect_kernel<<<1, 32>>>(x);
    packx_kernel<<<(NB * CIN * HW2 + 255) / 256, 256>>>(x);
    prepw_kernel<<<(COUT * KDIM + 255) / 256, 256>>>(wq);
    im2col_kernel<<<(NPIX * (KDIM / 4) + 255) / 256, 256>>>();

    cudaFuncSetAttribute(gemm_kernel, cudaFuncAttributeMaxDynamicSharedMemorySize, SM_TOTAL);
    gemm_kernel<<<M_TILES * N_TILES, THREADS, SM_TOTAL>>>(bias, d_out);
}

// round 6
// speedup vs baseline: 1.7636x; 1.7636x over previous
#include <cuda_runtime.h>
#include <cuda.h>
#include <cstdint>

// ============================================================
// QuantizedConv2d exact int conv via split-weight int8 mma.sync GEMM
//   x[8,128,56,56], w[256,128,3,3], bias[256], shift=16 (structural)
//   out[8,256,56,56] = (conv(x,w)+bias) >> 16
// w = (w>>8)*256 + (w&255): hi plane s8, lo plane u8; two s32 GEMMs,
// recombined in i64. Bit-exact.
// R5 evidence: im2col was 50us L1-bound. This version: NHWC repack with a
// zero halo (no bounds checks) + IMPLICIT im2col in the GEMM (K reordered as
// (kh,kw,cin)) -> the 29MB intermediate and its kernel are gone.
// Input storage width (i32/f32/i64/f64) still detected at runtime; output
// written as float for 4-byte worlds (R4 nan evidence).
// ============================================================

static constexpr int NB    = 8;
static constexpr int CIN   = 128;
static constexpr int COUT  = 256;
static constexpr int HW    = 56;
static constexpr int HW2   = HW * HW;           // 3136
static constexpr int NPIX  = NB * HW2;          // 25088
static constexpr int KDIM  = CIN * 9;           // 1152
static constexpr int SHIFT = 16;
static constexpr int PHW   = HW + 2;            // 58 (padded)

static constexpr int CTA_M = 128;               // pixels
static constexpr int CTA_N = 128;               // couts
static constexpr int KC    = 64;                // K chunk
static constexpr int NCHUNK = KDIM / KC;        // 18
static constexpr int M_TILES = NPIX / CTA_M;    // 196
static constexpr int N_TILES = COUT / CTA_N;    // 2
static constexpr int THREADS = 512;             // 16 warps: 4(M) x 4(N)

static constexpr int PITCH   = 80;
static constexpr int SM_TILE = 128 * PITCH;     // 10240
static constexpr int SM_STAGE = 3 * SM_TILE;    // 30720
static constexpr int SM_TOTAL = 2 * SM_STAGE;   // 61440

static constexpr int FLAG_I64 = 0, FLAG_I32 = 1, FLAG_F32 = 2, FLAG_F64 = 3;

// ---------------- scratch (device globals; allocation-free) ----------------
// NHWC padded image: [n][ph 0..57][pw 0..57][c], halo rows/cols zero.
__device__ __align__(128) int8_t g_Xt[(size_t)NB * PHW * PHW * CIN];  // 3.44MB
__device__ __align__(128) int8_t g_W[2 * (size_t)COUT * KDIM];        // hi|lo planes
__device__ int g_flag;

// ---------------- PTX helpers ----------------
__device__ __forceinline__ uint32_t smem_to_u32(const void* p) {
    uint32_t a;
    asm("{ .reg .u64 t; cvta.to.shared.u64 t, %1; cvt.u32.u64 %0, t; }" : "=r"(a) : "l"(p));
    return a;
}
__device__ __forceinline__ void cp16(uint32_t dst, const void* src) {
    asm volatile("cp.async.cg.shared.global [%0], [%1], 16;" :: "r"(dst), "l"(src));
}
#define CP_COMMIT() asm volatile("cp.async.commit_group;" ::: "memory")
#define CP_WAIT(n)  asm volatile("cp.async.wait_group %0;" :: "n"(n) : "memory")

__device__ __forceinline__ void ldsm_x4(uint32_t* r, uint32_t addr) {
    asm volatile("ldmatrix.sync.aligned.m8n8.x4.shared.b16 {%0,%1,%2,%3}, [%4];"
                 : "=r"(r[0]), "=r"(r[1]), "=r"(r[2]), "=r"(r[3]) : "r"(addr));
}
__device__ __forceinline__ void mma_s8s8(int* c, const uint32_t* a, const uint32_t* b) {
    asm volatile("mma.sync.aligned.m16n8k32.row.col.s32.s8.s8.s32 "
                 "{%0,%1,%2,%3}, {%4,%5,%6,%7}, {%8,%9}, {%0,%1,%2,%3};"
                 : "+r"(c[0]), "+r"(c[1]), "+r"(c[2]), "+r"(c[3])
                 : "r"(a[0]), "r"(a[1]), "r"(a[2]), "r"(a[3]), "r"(b[0]), "r"(b[1]));
}
__device__ __forceinline__ void mma_s8u8(int* c, const uint32_t* a, const uint32_t* b) {
    asm volatile("mma.sync.aligned.m16n8k32.row.col.s32.s8.u8.s32 "
                 "{%0,%1,%2,%3}, {%4,%5,%6,%7}, {%8,%9}, {%0,%1,%2,%3};"
                 : "+r"(c[0]), "+r"(c[1]), "+r"(c[2]), "+r"(c[3])
                 : "r"(a[0]), "r"(a[1]), "r"(a[2]), "r"(a[3]), "r"(b[0]), "r"(b[1]));
}

// ---------------- dtype detection (4-way) ----------------
__global__ void detect_kernel(const void* xraw) {
    if (threadIdx.x != 0 || blockIdx.x != 0) return;
    const int* w = (const int*)xraw;
    int signext = 0, small = 0, lozero = 0;
    for (int i = 0; i < 128; i++) {
        int lo = w[2 * i], hi = w[2 * i + 1];
        if (hi == (lo < 0 ? -1 : 0)) signext++;
        if (lo >= -256 && lo < 256 && hi >= -256 && hi < 256) small++;
        if (lo == 0) lozero++;
    }
    int f;
    if (signext >= 120)      f = FLAG_I64;
    else if (small >= 120)   f = FLAG_I32;
    else if (lozero >= 100)  f = FLAG_F64;
    else                     f = FLAG_F32;
    g_flag = f;
}

__device__ __forceinline__ long long load_val(const void* p, size_t idx, int flag) {
    if (flag == FLAG_I64) return ((const long long*)p)[idx];
    if (flag == FLAG_I32) return (long long)((const int*)p)[idx];
    if (flag == FLAG_F64) return __double2ll_rn(((const double*)p)[idx]);
    return (long long)__float2ll_rn(((const float*)p)[idx]);
}

// ---------------- kernel 1: pack + NCHW->NHWC transpose with halo ----------------
// One block per (n, padded_h). Halo rows write zeros; interior rows transpose
// via a smem tile. Reads of x coalesced (int words along w); writes coalesced.
__global__ void __launch_bounds__(256)
transpose_kernel(const void* __restrict__ x) {
    __shared__ int8_t s[CIN * (HW + 1)];   // pitch 57 to dodge bank conflicts
    int b  = blockIdx.x;
    int n  = b / PHW;
    int ph = b - n * PHW;
    int8_t* dst = g_Xt + ((size_t)(n * PHW + ph) * PHW) * CIN;
    int t = threadIdx.x;

    if (ph == 0 || ph == PHW - 1) {
        for (int i = t; i < PHW * CIN / 4; i += 256) ((int*)dst)[i] = 0;
        return;
    }
    int h = ph - 1;
    const int flag = g_flag;
    for (int i = t; i < CIN * HW; i += 256) {
        int c = i / HW, w = i - c * HW;
        long long v = load_val(x, ((size_t)(n * CIN + c) * HW + h) * HW + w, flag);
        s[c * (HW + 1) + w] = (int8_t)v;
    }
    __syncthreads();
    // write 58 padded-w pixels x 128 c, as 4B words [pw][c/4]
    for (int i = t; i < PHW * (CIN / 4); i += 256) {
        int pw = i >> 5;              // 0..57
        int c0 = (i & 31) * 4;
        uint32_t word = 0;
        if (pw >= 1 && pw <= HW) {
            int w = pw - 1;
            uchar4 u;
            u.x = (uint8_t)s[(c0 + 0) * (HW + 1) + w];
            u.y = (uint8_t)s[(c0 + 1) * (HW + 1) + w];
            u.z = (uint8_t)s[(c0 + 2) * (HW + 1) + w];
            u.w = (uint8_t)s[(c0 + 3) * (HW + 1) + w];
            word = *(uint32_t*)&u;
        }
        ((uint32_t*)dst)[i] = word;
    }
}

// ---------------- kernel 2: weight planes, K reordered to (khkw, cin) ----------------
__global__ void prepw_kernel(const void* __restrict__ wq) {
    int idx = blockIdx.x * blockDim.x + threadIdx.x;
    if (idx >= COUT * KDIM) return;
    int co = idx / KDIM;
    int r  = idx - co * KDIM;     // cin*9 + khkw (source order)
    int cin  = r / 9;
    int khkw = r - cin * 9;
    int kp = khkw * CIN + cin;    // target K order
    long long w = load_val(wq, idx, g_flag);
    g_W[(size_t)co * KDIM + kp] = (int8_t)(w >> 8);                        // hi s8
    g_W[(size_t)COUT * KDIM + (size_t)co * KDIM + kp] = (int8_t)(w & 255); // lo u8
}

// ---------------- kernel 3: implicit-im2col GEMM + epilogue ----------------
__global__ void __launch_bounds__(THREADS, 1)
gemm_kernel(const void* __restrict__ bias, void* __restrict__ outv) {
    extern __shared__ char smem[];
    const uint32_t smb = smem_to_u32(smem);
    const int tid  = threadIdx.x;
    const int lane = tid & 31;
    const int wrp  = tid >> 5;
    const int wm   = wrp & 3;
    const int wn   = wrp >> 2;

    const int mt = blockIdx.x >> 1;
    const int nt = blockIdx.x & 1;

    // per-thread cp.async assignments
    const int row = tid >> 2;     // 0..127 (A: pixel row; B: cout row)
    const int c16 = tid & 3;      // 16B column within 64B chunk

    // A row base in padded NHWC image (center tap), fixed across chunks
    {
    }
    const int p_ = mt * CTA_M + row;
    const int n_ = p_ / HW2;
    const int hw_ = p_ - n_ * HW2;
    const int h_ = hw_ / HW;
    const int w_ = hw_ - h_ * HW;
    const int8_t* Arow = g_Xt
        + ((size_t)((n_ * PHW + h_ + 1) * PHW + (w_ + 1))) * CIN + c16 * 16;
    const int8_t* Whi = g_W + (size_t)nt * CTA_N * KDIM + (size_t)row * KDIM + c16 * 16;
    const int8_t* Wlo = Whi + (size_t)COUT * KDIM;

    const uint32_t sA = smb + row * PITCH + c16 * 16;

    int acch[2][4][4];
    int accl[2][4][4];
#pragma unroll
    for (int mb = 0; mb < 2; mb++)
#pragma unroll
        for (int nb = 0; nb < 4; nb++)
#pragma unroll
            for (int i = 0; i < 4; i++) { acch[mb][nb][i] = 0; accl[mb][nb][i] = 0; }

    // chunk kc: khkw = kc>>1 (kh=khkw/3, kw=khkw%3), cin half = (kc&1)*64
    auto load_chunk = [&](int kc, int buf) {
        int khkw = kc >> 1;
        int kh = khkw / 3;
        int kw = khkw - kh * 3;
        const int8_t* asrc = Arow + ((kh - 1) * PHW + (kw - 1)) * CIN + (kc & 1) * KC;
        uint32_t sb = buf * SM_STAGE;
        cp16(sA + sb,                asrc);
        cp16(sA + sb + SM_TILE,      Whi + kc * KC);
        cp16(sA + sb + 2 * SM_TILE,  Wlo + kc * KC);
    };

    load_chunk(0, 0);
    CP_COMMIT();

    for (int kc = 0; kc < NCHUNK; kc++) {
        const int buf = kc & 1;
        if (kc + 1 < NCHUNK) {
            load_chunk(kc + 1, buf ^ 1);
            CP_COMMIT();
            CP_WAIT(1);
        } else {
            CP_WAIT(0);
        }
        __syncthreads();

        const uint32_t smA  = smb + buf * SM_STAGE;
        const uint32_t smBh = smA + SM_TILE;
        const uint32_t smBl = smA + 2 * SM_TILE;

#pragma unroll
        for (int ks = 0; ks < 2; ks++) {
            uint32_t a[2][4];
#pragma unroll
            for (int mb = 0; mb < 2; mb++) {
                uint32_t addr = smA + (uint32_t)((wm * 32 + mb * 16 + (lane & 15)) * PITCH
                                                 + (ks * 2 + (lane >> 4)) * 16);
                ldsm_x4(a[mb], addr);
            }
            uint32_t bh[2][4], bl[2][4];
#pragma unroll
            for (int nb2 = 0; nb2 < 2; nb2++) {
                uint32_t boff = (uint32_t)((wn * 32 + nb2 * 16 + (lane & 7) + ((lane >> 4) << 3)) * PITCH
                                           + (ks * 2 + ((lane >> 3) & 1)) * 16);
                ldsm_x4(bh[nb2], smBh + boff);
                ldsm_x4(bl[nb2], smBl + boff);
            }
#pragma unroll
            for (int mb = 0; mb < 2; mb++)
#pragma unroll
                for (int nb2 = 0; nb2 < 2; nb2++)
#pragma unroll
                    for (int q = 0; q < 2; q++) {
                        mma_s8s8(acch[mb][nb2 * 2 + q], a[mb], &bh[nb2][q * 2]);
                        mma_s8u8(accl[mb][nb2 * 2 + q], a[mb], &bl[nb2][q * 2]);
                    }
        }
        __syncthreads();
    }

    // ---- epilogue: combine hi/lo in i64, bias, shift, store ----
    const int flag = g_flag;
#pragma unroll
    for (int mb = 0; mb < 2; mb++) {
#pragma unroll
        for (int nb = 0; nb < 4; nb++) {
            int p0  = mt * CTA_M + wm * 32 + mb * 16 + (lane >> 2);
            int co0 = nt * CTA_N + wn * 32 + nb * 8 + (lane & 3) * 2;
#pragma unroll
            for (int i = 0; i < 4; i++) {
                int p  = p0 + ((i >= 2) ? 8 : 0);
                int co = co0 + (i & 1);
                long long b = load_val(bias, co, flag);
                long long v = (((long long)acch[mb][nb][i] << 8)
                               + (long long)accl[mb][nb][i] + b) >> SHIFT;
                int n  = p / HW2;
                int hw = p - n * HW2;
                size_t oi = ((size_t)(n * COUT + co)) * HW2 + hw;
                if (flag == FLAG_I64)      ((long long*)outv)[oi] = v;
                else if (flag == FLAG_F64) ((double*)outv)[oi] = (double)v;
                else                       ((float*)outv)[oi] = (float)v;
            }
        }
    }
}

// ---------------- launch ----------------
extern "C" void kernel_launch(void* const* d_in, const int* in_sizes, int n_in,
                              void* d_out, int out_size) {
    const void* x = nullptr; const void* wq = nullptr; const void* bias = nullptr;
    for (int i = 0; i < n_in; i++) {
        if (in_sizes[i] == NB * CIN * HW2)      x    = d_in[i];
        else if (in_sizes[i] == COUT * KDIM)    wq   = d_in[i];
        else if (in_sizes[i] == COUT)           bias = d_in[i];
    }
    (void)out_size;

    detect_kernel<<<1, 32>>>(x);
    transpose_kernel<<<NB * PHW, 256>>>(x);
    prepw_kernel<<<(COUT * KDIM + 255) / 256, 256>>>(wq);

    cudaFuncSetAttribute(gemm_kernel, cudaFuncAttributeMaxDynamicSharedMemorySize, SM_TOTAL);
    gemm_kernel<<<M_TILES * N_TILES, THREADS, SM_TOTAL>>>(bias, d_out);
}

// round 7
// speedup vs baseline: 1.8051x; 1.0236x over previous
#include <cuda_runtime.h>
#include <cuda.h>
#include <cstdint>

// ============================================================
// QuantizedConv2d exact int conv via split-weight int8 mma.sync GEMM
//   x[8,128,56,56], w[256,128,3,3], bias[256], shift=16 (structural)
//   out[8,256,56,56] = (conv(x,w)+bias) >> 16
// w = (w>>8)*256 + (w&255): hi plane s8, lo plane u8; two s32 GEMMs,
// recombined in i64. Bit-exact.
// NHWC repack with zero halo + implicit im2col GEMM (K = (kh,kw,cin)).
// R6 ncu: tensor=42%, occ=25% (1 CTA/SM), issue=19% -> latency-bound with
// 2 barriers/chunk. This round: 4-stage cp.async pipeline, ONE barrier per
// chunk, loads issued right after the sync.
// Input storage width (i32/f32/i64/f64) detected at runtime; output float
// for 4-byte worlds (R4 nan evidence).
// ============================================================

static constexpr int NB    = 8;
static constexpr int CIN   = 128;
static constexpr int COUT  = 256;
static constexpr int HW    = 56;
static constexpr int HW2   = HW * HW;           // 3136
static constexpr int NPIX  = NB * HW2;          // 25088
static constexpr int KDIM  = CIN * 9;           // 1152
static constexpr int SHIFT = 16;
static constexpr int PHW   = HW + 2;            // 58 (padded)

static constexpr int CTA_M = 128;               // pixels
static constexpr int CTA_N = 128;               // couts
static constexpr int KC    = 64;                // K chunk
static constexpr int NCHUNK = KDIM / KC;        // 18
static constexpr int M_TILES = NPIX / CTA_M;    // 196
static constexpr int N_TILES = COUT / CTA_N;    // 2
static constexpr int THREADS = 512;             // 16 warps: 4(M) x 4(N)

static constexpr int STAGES  = 4;
static constexpr int PITCH   = 80;
static constexpr int SM_TILE = 128 * PITCH;     // 10240
static constexpr int SM_STAGE = 3 * SM_TILE;    // 30720
static constexpr int SM_TOTAL = STAGES * SM_STAGE;  // 122880

static constexpr int FLAG_I64 = 0, FLAG_I32 = 1, FLAG_F32 = 2, FLAG_F64 = 3;

// ---------------- scratch (device globals; allocation-free) ----------------
__device__ __align__(128) int8_t g_Xt[(size_t)NB * PHW * PHW * CIN];  // 3.44MB
__device__ __align__(128) int8_t g_W[2 * (size_t)COUT * KDIM];        // hi|lo planes
__device__ int g_flag;

// ---------------- PTX helpers ----------------
__device__ __forceinline__ uint32_t smem_to_u32(const void* p) {
    uint32_t a;
    asm("{ .reg .u64 t; cvta.to.shared.u64 t, %1; cvt.u32.u64 %0, t; }" : "=r"(a) : "l"(p));
    return a;
}
__device__ __forceinline__ void cp16(uint32_t dst, const void* src) {
    asm volatile("cp.async.cg.shared.global [%0], [%1], 16;" :: "r"(dst), "l"(src));
}
#define CP_COMMIT() asm volatile("cp.async.commit_group;" ::: "memory")
#define CP_WAIT(n)  asm volatile("cp.async.wait_group %0;" :: "n"(n) : "memory")

__device__ __forceinline__ void ldsm_x4(uint32_t* r, uint32_t addr) {
    asm volatile("ldmatrix.sync.aligned.m8n8.x4.shared.b16 {%0,%1,%2,%3}, [%4];"
                 : "=r"(r[0]), "=r"(r[1]), "=r"(r[2]), "=r"(r[3]) : "r"(addr));
}
__device__ __forceinline__ void mma_s8s8(int* c, const uint32_t* a, const uint32_t* b) {
    asm volatile("mma.sync.aligned.m16n8k32.row.col.s32.s8.s8.s32 "
                 "{%0,%1,%2,%3}, {%4,%5,%6,%7}, {%8,%9}, {%0,%1,%2,%3};"
                 : "+r"(c[0]), "+r"(c[1]), "+r"(c[2]), "+r"(c[3])
                 : "r"(a[0]), "r"(a[1]), "r"(a[2]), "r"(a[3]), "r"(b[0]), "r"(b[1]));
}
__device__ __forceinline__ void mma_s8u8(int* c, const uint32_t* a, const uint32_t* b) {
    asm volatile("mma.sync.aligned.m16n8k32.row.col.s32.s8.u8.s32 "
                 "{%0,%1,%2,%3}, {%4,%5,%6,%7}, {%8,%9}, {%0,%1,%2,%3};"
                 : "+r"(c[0]), "+r"(c[1]), "+r"(c[2]), "+r"(c[3])
                 : "r"(a[0]), "r"(a[1]), "r"(a[2]), "r"(a[3]), "r"(b[0]), "r"(b[1]));
}

// ---------------- dtype detection (4-way) ----------------
__global__ void detect_kernel(const void* xraw) {
    if (threadIdx.x != 0 || blockIdx.x != 0) return;
    const int* w = (const int*)xraw;
    int signext = 0, small = 0, lozero = 0;
    for (int i = 0; i < 128; i++) {
        int lo = w[2 * i], hi = w[2 * i + 1];
        if (hi == (lo < 0 ? -1 : 0)) signext++;
        if (lo >= -256 && lo < 256 && hi >= -256 && hi < 256) small++;
        if (lo == 0) lozero++;
    }
    int f;
    if (signext >= 120)      f = FLAG_I64;
    else if (small >= 120)   f = FLAG_I32;
    else if (lozero >= 100)  f = FLAG_F64;
    else                     f = FLAG_F32;
    g_flag = f;
}

__device__ __forceinline__ long long load_val(const void* p, size_t idx, int flag) {
    if (flag == FLAG_I64) return ((const long long*)p)[idx];
    if (flag == FLAG_I32) return (long long)((const int*)p)[idx];
    if (flag == FLAG_F64) return __double2ll_rn(((const double*)p)[idx]);
    return (long long)__float2ll_rn(((const float*)p)[idx]);
}

// ---------------- kernel 1: pack + NCHW->NHWC transpose with halo ----------------
__global__ void __launch_bounds__(256)
transpose_kernel(const void* __restrict__ x) {
    __shared__ int8_t s[CIN * (HW + 1)];   // pitch 57 to dodge bank conflicts
    int b  = blockIdx.x;
    int n  = b / PHW;
    int ph = b - n * PHW;
    int8_t* dst = g_Xt + ((size_t)(n * PHW + ph) * PHW) * CIN;
    int t = threadIdx.x;

    if (ph == 0 || ph == PHW - 1) {
        for (int i = t; i < PHW * CIN / 4; i += 256) ((int*)dst)[i] = 0;
        return;
    }
    int h = ph - 1;
    const int flag = g_flag;
    for (int i = t; i < CIN * HW; i += 256) {
        int c = i / HW, w = i - c * HW;
        long long v = load_val(x, ((size_t)(n * CIN + c) * HW + h) * HW + w, flag);
        s[c * (HW + 1) + w] = (int8_t)v;
    }
    __syncthreads();
    for (int i = t; i < PHW * (CIN / 4); i += 256) {
        int pw = i >> 5;              // 0..57
        int c0 = (i & 31) * 4;
        uint32_t word = 0;
        if (pw >= 1 && pw <= HW) {
            int w = pw - 1;
            uchar4 u;
            u.x = (uint8_t)s[(c0 + 0) * (HW + 1) + w];
            u.y = (uint8_t)s[(c0 + 1) * (HW + 1) + w];
            u.z = (uint8_t)s[(c0 + 2) * (HW + 1) + w];
            u.w = (uint8_t)s[(c0 + 3) * (HW + 1) + w];
            word = *(uint32_t*)&u;
        }
        ((uint32_t*)dst)[i] = word;
    }
}

// ---------------- kernel 2: weight planes, K reordered to (khkw, cin) ----------------
__global__ void prepw_kernel(const void* __restrict__ wq) {
    int idx = blockIdx.x * blockDim.x + threadIdx.x;
    if (idx >= COUT * KDIM) return;
    int co = idx / KDIM;
    int r  = idx - co * KDIM;     // cin*9 + khkw (source order)
    int cin  = r / 9;
    int khkw = r - cin * 9;
    int kp = khkw * CIN + cin;    // target K order
    long long w = load_val(wq, idx, g_flag);
    g_W[(size_t)co * KDIM + kp] = (int8_t)(w >> 8);                        // hi s8
    g_W[(size_t)COUT * KDIM + (size_t)co * KDIM + kp] = (int8_t)(w & 255); // lo u8
}

// ---------------- kernel 3: implicit-im2col GEMM + epilogue ----------------
__global__ void __launch_bounds__(THREADS, 1)
gemm_kernel(const void* __restrict__ bias, void* __restrict__ outv) {
    extern __shared__ char smem[];
    const uint32_t smb = smem_to_u32(smem);
    const int tid  = threadIdx.x;
    const int lane = tid & 31;
    const int wrp  = tid >> 5;
    const int wm   = wrp & 3;
    const int wn   = wrp >> 2;

    const int mt = blockIdx.x >> 1;
    const int nt = blockIdx.x & 1;

    const int row = tid >> 2;     // 0..127
    const int c16 = tid & 3;

    const int p_ = mt * CTA_M + row;
    const int n_ = p_ / HW2;
    const int hw_ = p_ - n_ * HW2;
    const int h_ = hw_ / HW;
    const int w_ = hw_ - h_ * HW;
    const int8_t* Arow = g_Xt
        + ((size_t)((n_ * PHW + h_ + 1) * PHW + (w_ + 1))) * CIN + c16 * 16;
    const int8_t* Whi = g_W + (size_t)nt * CTA_N * KDIM + (size_t)row * KDIM + c16 * 16;
    const int8_t* Wlo = Whi + (size_t)COUT * KDIM;

    const uint32_t sA = smb + row * PITCH + c16 * 16;

    int acch[2][4][4];
    int accl[2][4][4];
#pragma unroll
    for (int mb = 0; mb < 2; mb++)
#pragma unroll
        for (int nb = 0; nb < 4; nb++)
#pragma unroll
            for (int i = 0; i < 4; i++) { acch[mb][nb][i] = 0; accl[mb][nb][i] = 0; }

    auto load_chunk = [&](int kc, int buf) {
        int khkw = kc >> 1;
        int kh = khkw / 3;
        int kw = khkw - kh * 3;
        const int8_t* asrc = Arow + ((kh - 1) * PHW + (kw - 1)) * CIN + (kc & 1) * KC;
        uint32_t sb = buf * SM_STAGE;
        cp16(sA + sb,                asrc);
        cp16(sA + sb + SM_TILE,      Whi + kc * KC);
        cp16(sA + sb + 2 * SM_TILE,  Wlo + kc * KC);
    };

    // prologue: fill STAGES-1 stages
#pragma unroll
    for (int s = 0; s < STAGES - 1; s++) { load_chunk(s, s); CP_COMMIT(); }

    for (int kc = 0; kc < NCHUNK; kc++) {
        CP_WAIT(STAGES - 2);
        __syncthreads();                       // single barrier per chunk
        {
            int nk = kc + STAGES - 1;
            if (nk < NCHUNK) load_chunk(nk, nk & (STAGES - 1));
            CP_COMMIT();                        // commit every iter (may be empty)
        }

        const uint32_t smA  = smb + (kc & (STAGES - 1)) * SM_STAGE;
        const uint32_t smBh = smA + SM_TILE;
        const uint32_t smBl = smA + 2 * SM_TILE;

#pragma unroll
        for (int ks = 0; ks < 2; ks++) {
            uint32_t a[2][4];
#pragma unroll
            for (int mb = 0; mb < 2; mb++) {
                uint32_t addr = smA + (uint32_t)((wm * 32 + mb * 16 + (lane & 15)) * PITCH
                                                 + (ks * 2 + (lane >> 4)) * 16);
                ldsm_x4(a[mb], addr);
            }
            uint32_t bh[2][4], bl[2][4];
#pragma unroll
            for (int nb2 = 0; nb2 < 2; nb2++) {
                uint32_t boff = (uint32_t)((wn * 32 + nb2 * 16 + (lane & 7) + ((lane >> 4) << 3)) * PITCH
                                           + (ks * 2 + ((lane >> 3) & 1)) * 16);
                ldsm_x4(bh[nb2], smBh + boff);
                ldsm_x4(bl[nb2], smBl + boff);
            }
#pragma unroll
            for (int mb = 0; mb < 2; mb++)
#pragma unroll
                for (int nb2 = 0; nb2 < 2; nb2++)
#pragma unroll
                    for (int q = 0; q < 2; q++) {
                        mma_s8s8(acch[mb][nb2 * 2 + q], a[mb], &bh[nb2][q * 2]);
                        mma_s8u8(accl[mb][nb2 * 2 + q], a[mb], &bl[nb2][q * 2]);
                    }
        }
    }

    // ---- epilogue: combine hi/lo in i64, bias, shift, store ----
    const int flag = g_flag;
#pragma unroll
    for (int mb = 0; mb < 2; mb++) {
#pragma unroll
        for (int nb = 0; nb < 4; nb++) {
            int p0  = mt * CTA_M + wm * 32 + mb * 16 + (lane >> 2);
            int co0 = nt * CTA_N + wn * 32 + nb * 8 + (lane & 3) * 2;
#pragma unroll
            for (int i = 0; i < 4; i++) {
                int p  = p0 + ((i >= 2) ? 8 : 0);
                int co = co0 + (i & 1);
                long long b = load_val(bias, co, flag);
                long long v = (((long long)acch[mb][nb][i] << 8)
                               + (long long)accl[mb][nb][i] + b) >> SHIFT;
                int n  = p / HW2;
                int hw = p - n * HW2;
                size_t oi = ((size_t)(n * COUT + co)) * HW2 + hw;
                if (flag == FLAG_I64)      ((long long*)outv)[oi] = v;
                else if (flag == FLAG_F64) ((double*)outv)[oi] = (double)v;
                else                       ((float*)outv)[oi] = (float)v;
            }
        }
    }
}

// ---------------- launch ----------------
extern "C" void kernel_launch(void* const* d_in, const int* in_sizes, int n_in,
                              void* d_out, int out_size) {
    const void* x = nullptr; const void* wq = nullptr; const void* bias = nullptr;
    for (int i = 0; i < n_in; i++) {
        if (in_sizes[i] == NB * CIN * HW2)      x    = d_in[i];
        else if (in_sizes[i] == COUT * KDIM)    wq   = d_in[i];
        else if (in_sizes[i] == COUT)           bias = d_in[i];
    }
    (void)out_size;

    detect_kernel<<<1, 32>>>(x);
    transpose_kernel<<<NB * PHW, 256>>>(x);
    prepw_kernel<<<(COUT * KDIM + 255) / 256, 256>>>(wq);

    cudaFuncSetAttribute(gemm_kernel, cudaFuncAttributeMaxDynamicSharedMemorySize, SM_TOTAL);
    gemm_kernel<<<M_TILES * N_TILES, THREADS, SM_TOTAL>>>(bias, d_out);
}